// round 14
// baseline (speedup 1.0000x reference)
#include <cuda_runtime.h>
#include <math.h>

#define BB 2
#define NN 8192
#define NPT (BB*NN)
#define KNN 10
#define GRID 16
#define GC (GRID*GRID*GRID)
#define HCELL 0.0625f
#define NBLKP 128
#define NTHRP 256
#define PEPS 1e-6f

// ---------------- device scratch ----------------
__device__ float4 g_sp4[NPT];
__device__ int    g_sidx[NPT];
__device__ int    g_cnt[BB*GC];      // INVARIANT: zero at kernel entry
__device__ int2   g_range[BB*GC];
__device__ int    g_cur[BB*GC];
__device__ double g_cacc[BB][4];
__device__ float  g_geom[NPT * 6];
__device__ int    g_mtype;
__device__ float  g_T;
__device__ unsigned g_barcnt = 0;
__device__ unsigned g_sense  = 0;

// ---------------- grid barrier ----------------
__device__ __forceinline__ void gridbar() {
    __syncthreads();
    if (threadIdx.x == 0) {
        __threadfence();
        unsigned gen = atomicAdd(&g_sense, 0u);
        if (atomicAdd(&g_barcnt, 1u) == NBLKP - 1) {
            g_barcnt = 0;
            __threadfence();
            atomicAdd(&g_sense, 1u);
        } else {
            while (atomicAdd(&g_sense, 0u) == gen) {}
        }
        __threadfence();
    }
    __syncthreads();
}

__device__ __forceinline__ int cell_of(float x, float y, float z) {
    int cx = min(GRID - 1, max(0, (int)(x * (float)GRID)));
    int cy = min(GRID - 1, max(0, (int)(y * (float)GRID)));
    int cz = min(GRID - 1, max(0, (int)(z * (float)GRID)));
    return (cz * GRID + cy) * GRID + cx;
}

__device__ __forceinline__ bool read_mask(const void* mp, int i, int mt) {
    if (mt & 1) return ((const unsigned char*)mp)[i] != 0;
    if (mt & 2) return ((const float*)mp)[i] != 0.0f;
    return ((const int*)mp)[i] != 0;
}

// ================= kernel 1: prep (identical to R11) =================
__global__ void __launch_bounds__(NTHRP)
k_prep(const float* __restrict__ pts, const void* __restrict__ mask) {
    const int tid = threadIdx.x;
    const int bid = blockIdx.x;
    const int gid = bid * NTHRP + tid;

    {
        bool act = gid < NPT;
        unsigned char mb = 0;
        if (act) {
            float x = pts[gid * 3 + 0], y = pts[gid * 3 + 1], z = pts[gid * 3 + 2];
            mb = ((const unsigned char*)mask)[gid];
            atomicAdd(&g_cnt[(gid >> 13) * GC + cell_of(x, y, z)], 1);
        }
        int r = gid & 3;
        unsigned m1 = __ballot_sync(0xFFFFFFFFu, act && (r == 1) && mb);
        unsigned m2 = __ballot_sync(0xFFFFFFFFu, act && (r >= 2) && mb);
        if ((tid & 31) == 0 && (m1 | m2))
            atomicOr(&g_mtype, (m1 ? 1 : 0) | (m2 ? 2 : 0));
    }
    gridbar();

    if (bid < BB) {
        __shared__ int part[NTHRP];
        int base = bid * GC + tid * 16;
        int loc[16]; int s = 0;
#pragma unroll
        for (int k = 0; k < 16; k++) { loc[k] = s; s += g_cnt[base + k]; }
        part[tid] = s;
        __syncthreads();
        for (int d = 1; d < NTHRP; d <<= 1) {
            int v = (tid >= d) ? part[tid - d] : 0;
            __syncthreads();
            part[tid] += v;
            __syncthreads();
        }
        int off = part[tid] - s;
#pragma unroll
        for (int k = 0; k < 16; k++) {
            int st = off + loc[k];
            int ln = g_cnt[base + k];
            g_range[base + k] = make_int2(st, st + ln);
            g_cur[base + k]   = st;
            g_cnt[base + k]   = 0;
        }
        if (gid == 0) {
            for (int b = 0; b < BB; b++)
                for (int c = 0; c < 4; c++) g_cacc[b][c] = 0.0;
            const float R = 0.02f;
            float t = __fmul_rn(R, R);
            while (__fsqrt_rn(t) >= R) t = __uint_as_float(__float_as_uint(t) - 1u);
            for (;;) {
                float nt = __uint_as_float(__float_as_uint(t) + 1u);
                if (__fsqrt_rn(nt) < R) t = nt; else break;
            }
            g_T = t;
        }
    }
    gridbar();

    if (gid < NPT) {
        int mt = g_mtype;
        float x = pts[gid * 3 + 0], y = pts[gid * 3 + 1], z = pts[gid * 3 + 2];
        float sq = __fadd_rn(__fadd_rn(__fmul_rn(x, x), __fmul_rn(y, y)), __fmul_rn(z, z));
        int b = gid >> 13;
        int cell = b * GC + cell_of(x, y, z);
        bool mk = read_mask(mask, gid, mt);
        float wv = mk ? __uint_as_float(__float_as_uint(sq) | 0x80000000u) : sq;
        int pos = atomicAdd(&g_cur[cell], 1);
        int dst = b * NN + pos;
        g_sp4[dst]  = make_float4(x, y, z, wv);
        g_sidx[dst] = gid;
        double vx = mk ? (double)x : 0.0, vy = mk ? (double)y : 0.0;
        double vz = mk ? (double)z : 0.0, vc = mk ? 1.0 : 0.0;
#pragma unroll
        for (int o = 16; o > 0; o >>= 1) {
            vx += __shfl_down_sync(0xFFFFFFFFu, vx, o);
            vy += __shfl_down_sync(0xFFFFFFFFu, vy, o);
            vz += __shfl_down_sync(0xFFFFFFFFu, vz, o);
            vc += __shfl_down_sync(0xFFFFFFFFu, vc, o);
        }
        if ((tid & 31) == 0) {
            atomicAdd(&g_cacc[b][0], vx);
            atomicAdd(&g_cacc[b][1], vy);
            atomicAdd(&g_cacc[b][2], vz);
            atomicAdd(&g_cacc[b][3], vc);
        }
    }
}

// ---------------- analytic eigenvalues of symmetric 3x3 (fp64) ----------------
__device__ __forceinline__ float curv_from_cov(float c00, float c01, float c02,
                                               float c11, float c12, float c22) {
    double a00 = c00, a01 = c01, a02 = c02, a11 = c11, a12 = c12, a22 = c22;
    double p1 = a01 * a01 + a02 * a02 + a12 * a12;
    double q  = (a00 + a11 + a22) / 3.0;
    double d0 = a00 - q, d1 = a11 - q, d2v = a22 - q;
    double p2 = d0 * d0 + d1 * d1 + d2v * d2v + 2.0 * p1;
    double emin, emax;
    if (!(p2 > 0.0)) { emin = q; emax = q; }
    else {
        double p = sqrt(p2 / 6.0);
        double ip = 1.0 / p;
        double b00 = d0 * ip, b11 = d1 * ip, b22 = d2v * ip;
        double b01 = a01 * ip, b02 = a02 * ip, b12 = a12 * ip;
        double detB = b00 * (b11 * b22 - b12 * b12)
                    - b01 * (b01 * b22 - b12 * b02)
                    + b02 * (b01 * b12 - b11 * b02);
        double r = 0.5 * detB;
        r = fmin(1.0, fmax(-1.0, r));
        double phi = acos(r) / 3.0;
        emax = q + 2.0 * p * cos(phi);
        emin = q + 2.0 * p * cos(phi + 2.0943951023931953);
    }
    float e0 = (float)emin, e2 = (float)emax;
    return e0 / (e2 + 1e-8f);
}

// ================= kernel 2: 16-lane cooperative exact 10-NN + density =================
__global__ void __launch_bounds__(256) k_geom2() {
    const int gt = blockIdx.x * 256 + threadIdx.x;   // 262144 threads
    const int p   = gt >> 4;
    const int l16 = gt & 15;
    const int b   = p >> 13;
    const int s   = p & (NN - 1);
    const int boff  = b * NN;
    const int cbase = b * GC;
    const unsigned gmask = 0xFFFFu << ((threadIdx.x & 31) & ~15);

    float4 pi = __ldg(&g_sp4[boff + s]);
    const float pix = pi.x, piy = pi.y, piz = pi.z, piw = fabsf(pi.w);
    const int orig  = g_sidx[boff + s];
    const float Tloc = g_T;

    const int cix = min(GRID - 1, max(0, (int)(pix * (float)GRID)));
    const int ciy = min(GRID - 1, max(0, (int)(piy * (float)GRID)));
    const int ciz = min(GRID - 1, max(0, (int)(piz * (float)GRID)));

    float r_est = 0.075f;
#pragma unroll
    for (int it = 0; it < 2; it++) {
        float fx = (fminf(pix + r_est, 1.0f) - fmaxf(pix - r_est, 0.0f)) / (2.0f * r_est);
        float fy = (fminf(piy + r_est, 1.0f) - fmaxf(piy - r_est, 0.0f)) / (2.0f * r_est);
        float fz = (fminf(piz + r_est, 1.0f) - fmaxf(piz - r_est, 0.0f)) / (2.0f * r_est);
        r_est = cbrtf(6.4e-4f / fmaxf(fx * fy * fz, 0.125f));
    }
    const float t_est = r_est * r_est;
    const unsigned long long GATE_EST =
        ((unsigned long long)__float_as_uint(t_est) << 32) | 0xFFFFFFFFull;
    const unsigned long long GATE_INF = 0xFFFFFFFFFFFFFFFFull;

    unsigned long long best[KNN];
    int cnt;
    float c00, c01, c02, c11, c12, c22;
    unsigned long long d10key;

    for (int R = 2;; R++) {
        bool scanned = false;

        if (R == 2) {
            // gated fast path: each of 16 lanes preloads up to 2 pruned row ranges
#pragma unroll
            for (int k = 0; k < KNN; k++) best[k] = GATE_EST;
            cnt = 0;
            int passes = 0;

            const int x0 = max(cix - 2, 0), x1 = min(cix + 2, GRID - 1);
            int rjst[2], rjen[2];
#pragma unroll
            for (int i = 0; i < 2; i++) {
                rjst[i] = 0; rjen[i] = 0;
                int q = l16 + 16 * i;
                if (q < 25) {
                    int zz = ciz + q / 5 - 2, yy = ciy + q % 5 - 2;
                    if ((unsigned)zz < GRID && (unsigned)yy < GRID) {
                        float zlo = (float)zz * HCELL, zhi = zlo + HCELL;
                        float ylo = (float)yy * HCELL, yhi = ylo + HCELL;
                        float dzl = fmaxf(0.0f, fmaxf(zlo - piz, piz - zhi));
                        float dyl = fmaxf(0.0f, fmaxf(ylo - piy, piy - yhi));
                        float rb2 = dzl * dzl + dyl * dyl;
                        if (rb2 <= t_est + PEPS) {
                            float xr = sqrtf(t_est + PEPS - rb2);
                            int xlo = (int)((pix - xr) * (float)GRID);
                            int xhi = (int)((pix + xr) * (float)GRID);
                            int xa = max(x0, xlo), xb = min(x1, xhi);
                            int crow = cbase + (zz * GRID + yy) * GRID;
                            rjst[i] = __ldg(&g_range[crow + xa].x);
                            rjen[i] = __ldg(&g_range[crow + xb].y);
                        }
                    }
                }
            }
#pragma unroll
            for (int i = 0; i < 2; i++) {
#pragma unroll 2
                for (int j = rjst[i]; j < rjen[i]; ++j) {
                    float4 pj = __ldg(&g_sp4[boff + j]);
                    float sqj = fabsf(pj.w);
                    float Tv  = (__float_as_uint(pj.w) & 0x80000000u)
                                ? Tloc : __int_as_float(0xff800000);
                    float dot = fmaf(pix, pj.x, fmaf(piy, pj.y, piz * pj.z));
                    float d2  = fmaf(-2.0f, dot, piw + sqj);
                    if (d2 <= Tv) cnt++;
                    float d2c = fmaxf(d2, 0.0f);
                    if (d2c < t_est) passes++;
                    unsigned long long key =
                        ((unsigned long long)__float_as_uint(d2c) << 32) | (unsigned)j;
                    if (key < best[KNN - 1]) {
#pragma unroll
                        for (int k = 0; k < KNN; k++) {
                            if (key < best[k]) {
                                unsigned long long tmp = best[k]; best[k] = key; key = tmp;
                            }
                        }
                    }
                }
            }

            int pall = passes;
            pall += __shfl_xor_sync(gmask, pall, 1);
            pall += __shfl_xor_sync(gmask, pall, 2);
            pall += __shfl_xor_sync(gmask, pall, 4);
            pall += __shfl_xor_sync(gmask, pall, 8);
            if (pall >= KNN) scanned = true;
        }

        if (!scanned) {
#pragma unroll
            for (int k = 0; k < KNN; k++) best[k] = GATE_INF;
            cnt = 0;

            const int W = 2 * R + 1;
            const int nr = W * W;
            const int x0 = max(cix - R, 0), x1 = min(cix + R, GRID - 1);
            int qy = l16, qz = 0;
            while (qy >= W) { qy -= W; qz++; }

            for (int q = l16; q < nr; q += 16) {
                int zz = ciz + qz - R, yy = ciy + qy - R;
                if ((unsigned)zz < GRID && (unsigned)yy < GRID) {
                    int crow = cbase + (zz * GRID + yy) * GRID;
                    int jst = __ldg(&g_range[crow + x0].x);
                    int jen = __ldg(&g_range[crow + x1].y);
                    for (int j = jst; j < jen; ++j) {
                        float4 pj = __ldg(&g_sp4[boff + j]);
                        float sqj = fabsf(pj.w);
                        float Tv  = (__float_as_uint(pj.w) & 0x80000000u)
                                    ? Tloc : __int_as_float(0xff800000);
                        float dot = fmaf(pix, pj.x, fmaf(piy, pj.y, piz * pj.z));
                        float d2  = fmaf(-2.0f, dot, piw + sqj);
                        if (d2 <= Tv) cnt++;
                        float d2c = fmaxf(d2, 0.0f);
                        unsigned long long key =
                            ((unsigned long long)__float_as_uint(d2c) << 32) | (unsigned)j;
                        if (key < best[KNN - 1]) {
#pragma unroll
                            for (int k = 0; k < KNN; k++) {
                                if (key < best[k]) {
                                    unsigned long long tmp = best[k]; best[k] = key; key = tmp;
                                }
                            }
                        }
                    }
                }
                qy += 16;
                while (qy >= W) { qy -= W; qz++; }
            }
        }

        // merge top-10 across the 16 lanes; owner pops + accumulates covariance
        c00 = c01 = c02 = c11 = c12 = c22 = 0.0f;
        d10key = GATE_INF;
#pragma unroll
        for (int round = 0; round < KNN; round++) {
            unsigned long long m = best[0];
            m = min(m, __shfl_xor_sync(gmask, m, 1));
            m = min(m, __shfl_xor_sync(gmask, m, 2));
            m = min(m, __shfl_xor_sync(gmask, m, 4));
            m = min(m, __shfl_xor_sync(gmask, m, 8));
            bool real = ((unsigned)(m & 0xFFFFFFFFull)) != 0xFFFFFFFFu;
            if (m == best[0] && real) {
                int j = (int)(unsigned)(m & 0xFFFFFFFFull);
                float4 q = __ldg(&g_sp4[boff + j]);
                float dx = q.x - pix, dy = q.y - piy, dz = q.z - piz;
                c00 = fmaf(dx, dx, c00); c01 = fmaf(dx, dy, c01); c02 = fmaf(dx, dz, c02);
                c11 = fmaf(dy, dy, c11); c12 = fmaf(dy, dz, c12); c22 = fmaf(dz, dz, c22);
#pragma unroll
                for (int k = 0; k < KNN - 1; k++) best[k] = best[k + 1];
                best[KNN - 1] = GATE_INF;
            }
            d10key = m;
        }

        float g = __int_as_float(0x7f800000);
        if (cix - R > 0)        g = fminf(g, pix - (float)(cix - R) * HCELL);
        if (cix + R < GRID - 1) g = fminf(g, (float)(cix + R + 1) * HCELL - pix);
        if (ciy - R > 0)        g = fminf(g, piy - (float)(ciy - R) * HCELL);
        if (ciy + R < GRID - 1) g = fminf(g, (float)(ciy + R + 1) * HCELL - piy);
        if (ciz - R > 0)        g = fminf(g, piz - (float)(ciz - R) * HCELL);
        if (ciz + R < GRID - 1) g = fminf(g, (float)(ciz + R + 1) * HCELL - piz);
        bool filled = ((unsigned)(d10key & 0xFFFFFFFFull)) != 0xFFFFFFFFu;
        float d10 = __uint_as_float((unsigned)(d10key >> 32));
        if (filled && d10 < g * g) break;
        if (R >= GRID) break;
    }

    // reduce density + covariance across the 16 lanes
#pragma unroll
    for (int o = 1; o < 16; o <<= 1) {
        cnt += __shfl_xor_sync(gmask, cnt, o);
        c00 += __shfl_xor_sync(gmask, c00, o);
        c01 += __shfl_xor_sync(gmask, c01, o);
        c02 += __shfl_xor_sync(gmask, c02, o);
        c11 += __shfl_xor_sync(gmask, c11, o);
        c12 += __shfl_xor_sync(gmask, c12, o);
        c22 += __shfl_xor_sync(gmask, c22, o);
    }

    if (l16 == 0) {
        c00 = __fdiv_rn(c00, 10.0f); c01 = __fdiv_rn(c01, 10.0f); c02 = __fdiv_rn(c02, 10.0f);
        c11 = __fdiv_rn(c11, 10.0f); c12 = __fdiv_rn(c12, 10.0f); c22 = __fdiv_rn(c22, 10.0f);
        float curv = curv_from_cov(c00, c01, c02, c11, c12, c22);

        double cm   = g_cacc[b][3];
        double cden = cm > 1.0 ? cm : 1.0;
        float cx = (float)(g_cacc[b][0] / cden);
        float cy = (float)(g_cacc[b][1] / cden);
        float cz = (float)(g_cacc[b][2] / cden);
        float rx = pix - cx, ry = piy - cy, rz = piz - cz;
        float distc = __fsqrt_rn(__fadd_rn(__fadd_rn(__fmul_rn(rx, rx), __fmul_rn(ry, ry)), __fmul_rn(rz, rz)));
        float horiz = __fsqrt_rn(__fadd_rn(__fmul_rn(rx, rx), __fmul_rn(ry, ry)));
        float rad   = atan2f(ry, rx);

        bool valid = cm > 0.0;
        g_geom[orig * 6 + 0] = valid ? distc : 0.0f;
        g_geom[orig * 6 + 1] = valid ? rz    : 0.0f;
        g_geom[orig * 6 + 2] = valid ? horiz : 0.0f;
        g_geom[orig * 6 + 3] = valid ? (float)cnt : 0.0f;
        g_geom[orig * 6 + 4] = valid ? curv  : 0.0f;
        g_geom[orig * 6 + 5] = valid ? rad   : 0.0f;
    }
}

// ================= kernel 3: MLP via mma.sync tf32, 512 thr, weights from L1 =================
#define XS   76
#define HS   132
#define OX   0
#define OH   9728
#define OB1  26624
#define OB2  26752
#define SMEM_MMA 107520

__device__ __forceinline__ unsigned to_tf32u(float v) {
    unsigned r; asm("cvt.rna.tf32.f32 %0, %1;" : "=r"(r) : "f"(v)); return r;
}
__device__ __forceinline__ void mma8(float* c, unsigned a0, unsigned a1, unsigned a2,
                                     unsigned a3, unsigned b0, unsigned b1) {
    asm volatile(
        "mma.sync.aligned.m16n8k8.row.col.f32.tf32.tf32.f32 "
        "{%0,%1,%2,%3}, {%4,%5,%6,%7}, {%8,%9}, {%0,%1,%2,%3};"
        : "+f"(c[0]), "+f"(c[1]), "+f"(c[2]), "+f"(c[3])
        : "r"(a0), "r"(a1), "r"(a2), "r"(a3), "r"(b0), "r"(b1));
}

__global__ void __launch_bounds__(512)
k_mlp_mma(const float* __restrict__ feat,
          const float* __restrict__ W1, const float* __restrict__ b1,
          const float* __restrict__ W2, const float* __restrict__ b2,
          float* __restrict__ out) {
    extern __shared__ float sm[];
    const int tid = threadIdx.x;
    const int wid = tid >> 5;
    const int lane = tid & 31;
    const int lr = lane >> 2;          // 0..7
    const int lc = lane & 3;           // 0..3
    const int wrow  = (wid >> 1) * 16; // warp pair's 16-row stripe
    const int nhalf = (wid & 1) * 64;  // warp's n-half
    const int m0 = blockIdx.x * 128;

    // ---- stage X (tf32) + biases ----
    for (int i = tid; i < 128 * 64; i += 512) {
        int r = i >> 6, c = i & 63;
        sm[OX + r * XS + c] = __uint_as_float(to_tf32u(feat[(size_t)(m0 + r) * 64 + c]));
    }
    for (int i = tid; i < 128 * 6; i += 512) {
        int r = i / 6, c = i % 6;
        sm[OX + r * XS + 64 + c] = __uint_as_float(to_tf32u(g_geom[(size_t)(m0 + r) * 6 + c]));
    }
    if (tid < 256) {                   // X pad cols 70,71 = 0
        int r = tid >> 1, c = 70 + (tid & 1);
        sm[OX + r * XS + c] = 0.0f;
    }
    if (tid < 128) { sm[OB1 + tid] = b1[tid]; sm[OB2 + tid] = b2[tid]; }
    __syncthreads();

    float acc[8][4];
#pragma unroll
    for (int t = 0; t < 8; t++)
#pragma unroll
        for (int c = 0; c < 4; c++) acc[t][c] = 0.0f;

    // ---- layer 1: X[128x72] @ W1t (B from global via L1) ----
    const float* xa = sm + OX + (wrow + lr) * XS;
    for (int ks = 0; ks < 8; ks++) {   // k-steps 0..7: all W1 rows < 64+4 = valid
        int k0 = ks * 8;
        unsigned a0 = __float_as_uint(xa[k0 + lc]);
        unsigned a1 = __float_as_uint(xa[8 * XS + k0 + lc]);
        unsigned a2 = __float_as_uint(xa[k0 + lc + 4]);
        unsigned a3 = __float_as_uint(xa[8 * XS + k0 + lc + 4]);
        const float* wb = W1 + (k0 + lc) * 128 + nhalf + lr;
#pragma unroll
        for (int t = 0; t < 8; t++) {
            unsigned b0  = to_tf32u(__ldg(wb + t * 8));
            unsigned b1r = to_tf32u(__ldg(wb + 4 * 128 + t * 8));
            mma8(acc[t], a0, a1, a2, a3, b0, b1r);
        }
    }
    {   // k-step 8: W1 rows 68..71 — rows >= 70 are zero-pad
        int k0 = 64;
        unsigned a0 = __float_as_uint(xa[k0 + lc]);
        unsigned a1 = __float_as_uint(xa[8 * XS + k0 + lc]);
        unsigned a2 = __float_as_uint(xa[k0 + lc + 4]);
        unsigned a3 = __float_as_uint(xa[8 * XS + k0 + lc + 4]);
        const float* wb0 = W1 + (k0 + lc) * 128 + nhalf + lr;      // rows 64..67
        const float* wb1 = W1 + (k0 + lc + 4) * 128 + nhalf + lr;  // rows 68..71
        bool v1 = (k0 + lc + 4) < 70;
#pragma unroll
        for (int t = 0; t < 8; t++) {
            unsigned b0  = to_tf32u(__ldg(wb0 + t * 8));
            unsigned b1r = v1 ? to_tf32u(__ldg(wb1 + t * 8)) : 0u;
            mma8(acc[t], a0, a1, a2, a3, b0, b1r);
        }
    }

    // ---- epilogue 1: bias + relu -> H (tf32) ----
#pragma unroll
    for (int t = 0; t < 8; t++) {
        int n0 = nhalf + t * 8 + 2 * lc;
        float bv0 = sm[OB1 + n0], bv1 = sm[OB1 + n0 + 1];
        float2 h0, h1;
        h0.x = __uint_as_float(to_tf32u(fmaxf(acc[t][0] + bv0, 0.0f)));
        h0.y = __uint_as_float(to_tf32u(fmaxf(acc[t][1] + bv1, 0.0f)));
        h1.x = __uint_as_float(to_tf32u(fmaxf(acc[t][2] + bv0, 0.0f)));
        h1.y = __uint_as_float(to_tf32u(fmaxf(acc[t][3] + bv1, 0.0f)));
        *(float2*)&sm[OH + (wrow + lr) * HS + n0]     = h0;
        *(float2*)&sm[OH + (wrow + lr + 8) * HS + n0] = h1;
    }
    __syncthreads();   // warp pairs wrote complementary n-halves of shared rows

#pragma unroll
    for (int t = 0; t < 8; t++)
#pragma unroll
        for (int c = 0; c < 4; c++) acc[t][c] = 0.0f;

    // ---- layer 2: H[128x128] @ W2t ----
    const float* ha = sm + OH + (wrow + lr) * HS;
    for (int ks = 0; ks < 16; ks++) {
        int k0 = ks * 8;
        unsigned a0 = __float_as_uint(ha[k0 + lc]);
        unsigned a1 = __float_as_uint(ha[8 * HS + k0 + lc]);
        unsigned a2 = __float_as_uint(ha[k0 + lc + 4]);
        unsigned a3 = __float_as_uint(ha[8 * HS + k0 + lc + 4]);
        const float* wb = W2 + (k0 + lc) * 128 + nhalf + lr;
#pragma unroll
        for (int t = 0; t < 8; t++) {
            unsigned b0  = to_tf32u(__ldg(wb + t * 8));
            unsigned b1r = to_tf32u(__ldg(wb + 4 * 128 + t * 8));
            mma8(acc[t], a0, a1, a2, a3, b0, b1r);
        }
    }

    // ---- epilogue 2: bias + relu -> global ----
#pragma unroll
    for (int t = 0; t < 8; t++) {
        int n0 = nhalf + t * 8 + 2 * lc;
        float bv0 = sm[OB2 + n0], bv1 = sm[OB2 + n0 + 1];
        float2 o0, o1;
        o0.x = fmaxf(acc[t][0] + bv0, 0.0f);
        o0.y = fmaxf(acc[t][1] + bv1, 0.0f);
        o1.x = fmaxf(acc[t][2] + bv0, 0.0f);
        o1.y = fmaxf(acc[t][3] + bv1, 0.0f);
        *(float2*)&out[(size_t)(m0 + wrow + lr) * 128 + n0]     = o0;
        *(float2*)&out[(size_t)(m0 + wrow + lr + 8) * 128 + n0] = o1;
    }
}

// ---------------- launch ----------------
extern "C" void kernel_launch(void* const* d_in, const int* in_sizes, int n_in,
                              void* d_out, int out_size) {
    const float* points = (const float*)d_in[0];
    const float* feat   = (const float*)d_in[1];
    const void*  mask   = d_in[2];
    const float* W1     = (const float*)d_in[3];
    const float* b1     = (const float*)d_in[4];
    const float* W2     = (const float*)d_in[5];
    const float* b2     = (const float*)d_in[6];
    float* out = (float*)d_out;

    cudaFuncSetAttribute(k_mlp_mma, cudaFuncAttributeMaxDynamicSharedMemorySize, SMEM_MMA);

    k_prep   <<<NBLKP, NTHRP>>>(points, mask);
    k_geom2  <<<(NPT * 16) / 256, 256>>>();
    k_mlp_mma<<<NPT / 128, 512, SMEM_MMA>>>(feat, W1, b1, W2, b2, out);
}

// round 15
// speedup vs baseline: 1.3830x; 1.3830x over previous
#include <cuda_runtime.h>
#include <math.h>

#define BB 2
#define NN 8192
#define NPT (BB*NN)
#define KNN 10
#define GRID 16
#define GC (GRID*GRID*GRID)
#define HCELL 0.0625f
#define NBLKP 128
#define NTHRP 256
#define PEPS 1e-6f

// ---------------- device scratch ----------------
__device__ float4 g_sp4[NPT];
__device__ int    g_sidx[NPT];
__device__ int    g_cnt[BB*GC];      // INVARIANT: zero at kernel entry
__device__ int2   g_range[BB*GC];
__device__ int    g_cur[BB*GC];
__device__ double g_cacc[BB][4];
__device__ float  g_geom[NPT * 6];
__device__ int    g_mtype;
__device__ float  g_T;
__device__ unsigned g_barcnt = 0;
__device__ unsigned g_sense  = 0;

// ---------------- grid barrier ----------------
__device__ __forceinline__ void gridbar() {
    __syncthreads();
    if (threadIdx.x == 0) {
        __threadfence();
        unsigned gen = atomicAdd(&g_sense, 0u);
        if (atomicAdd(&g_barcnt, 1u) == NBLKP - 1) {
            g_barcnt = 0;
            __threadfence();
            atomicAdd(&g_sense, 1u);
        } else {
            while (atomicAdd(&g_sense, 0u) == gen) {}
        }
        __threadfence();
    }
    __syncthreads();
}

__device__ __forceinline__ int cell_of(float x, float y, float z) {
    int cx = min(GRID - 1, max(0, (int)(x * (float)GRID)));
    int cy = min(GRID - 1, max(0, (int)(y * (float)GRID)));
    int cz = min(GRID - 1, max(0, (int)(z * (float)GRID)));
    return (cz * GRID + cy) * GRID + cx;
}

__device__ __forceinline__ bool read_mask(const void* mp, int i, int mt) {
    if (mt & 1) return ((const unsigned char*)mp)[i] != 0;
    if (mt & 2) return ((const float*)mp)[i] != 0.0f;
    return ((const int*)mp)[i] != 0;
}

// ================= kernel 1: prep (identical to R13) =================
__global__ void __launch_bounds__(NTHRP)
k_prep(const float* __restrict__ pts, const void* __restrict__ mask) {
    const int tid = threadIdx.x;
    const int bid = blockIdx.x;
    const int gid = bid * NTHRP + tid;

    {
        bool act = gid < NPT;
        unsigned char mb = 0;
        if (act) {
            float x = pts[gid * 3 + 0], y = pts[gid * 3 + 1], z = pts[gid * 3 + 2];
            mb = ((const unsigned char*)mask)[gid];
            atomicAdd(&g_cnt[(gid >> 13) * GC + cell_of(x, y, z)], 1);
        }
        int r = gid & 3;
        unsigned m1 = __ballot_sync(0xFFFFFFFFu, act && (r == 1) && mb);
        unsigned m2 = __ballot_sync(0xFFFFFFFFu, act && (r >= 2) && mb);
        if ((tid & 31) == 0 && (m1 | m2))
            atomicOr(&g_mtype, (m1 ? 1 : 0) | (m2 ? 2 : 0));
    }
    gridbar();

    if (bid < BB) {
        __shared__ int part[NTHRP];
        int base = bid * GC + tid * 16;
        int loc[16]; int s = 0;
#pragma unroll
        for (int k = 0; k < 16; k++) { loc[k] = s; s += g_cnt[base + k]; }
        part[tid] = s;
        __syncthreads();
        for (int d = 1; d < NTHRP; d <<= 1) {
            int v = (tid >= d) ? part[tid - d] : 0;
            __syncthreads();
            part[tid] += v;
            __syncthreads();
        }
        int off = part[tid] - s;
#pragma unroll
        for (int k = 0; k < 16; k++) {
            int st = off + loc[k];
            int ln = g_cnt[base + k];
            g_range[base + k] = make_int2(st, st + ln);
            g_cur[base + k]   = st;
            g_cnt[base + k]   = 0;
        }
        if (gid == 0) {
            for (int b = 0; b < BB; b++)
                for (int c = 0; c < 4; c++) g_cacc[b][c] = 0.0;
            const float R = 0.02f;
            float t = __fmul_rn(R, R);
            while (__fsqrt_rn(t) >= R) t = __uint_as_float(__float_as_uint(t) - 1u);
            for (;;) {
                float nt = __uint_as_float(__float_as_uint(t) + 1u);
                if (__fsqrt_rn(nt) < R) t = nt; else break;
            }
            g_T = t;
        }
    }
    gridbar();

    if (gid < NPT) {
        int mt = g_mtype;
        float x = pts[gid * 3 + 0], y = pts[gid * 3 + 1], z = pts[gid * 3 + 2];
        float sq = __fadd_rn(__fadd_rn(__fmul_rn(x, x), __fmul_rn(y, y)), __fmul_rn(z, z));
        int b = gid >> 13;
        int cell = b * GC + cell_of(x, y, z);
        bool mk = read_mask(mask, gid, mt);
        float wv = mk ? __uint_as_float(__float_as_uint(sq) | 0x80000000u) : sq;
        int pos = atomicAdd(&g_cur[cell], 1);
        int dst = b * NN + pos;
        g_sp4[dst]  = make_float4(x, y, z, wv);
        g_sidx[dst] = gid;
        double vx = mk ? (double)x : 0.0, vy = mk ? (double)y : 0.0;
        double vz = mk ? (double)z : 0.0, vc = mk ? 1.0 : 0.0;
#pragma unroll
        for (int o = 16; o > 0; o >>= 1) {
            vx += __shfl_down_sync(0xFFFFFFFFu, vx, o);
            vy += __shfl_down_sync(0xFFFFFFFFu, vy, o);
            vz += __shfl_down_sync(0xFFFFFFFFu, vz, o);
            vc += __shfl_down_sync(0xFFFFFFFFu, vc, o);
        }
        if ((tid & 31) == 0) {
            atomicAdd(&g_cacc[b][0], vx);
            atomicAdd(&g_cacc[b][1], vy);
            atomicAdd(&g_cacc[b][2], vz);
            atomicAdd(&g_cacc[b][3], vc);
        }
    }
}

// ---------------- analytic eigenvalues of symmetric 3x3 (fp64) ----------------
__device__ __forceinline__ float curv_from_cov(float c00, float c01, float c02,
                                               float c11, float c12, float c22) {
    double a00 = c00, a01 = c01, a02 = c02, a11 = c11, a12 = c12, a22 = c22;
    double p1 = a01 * a01 + a02 * a02 + a12 * a12;
    double q  = (a00 + a11 + a22) / 3.0;
    double d0 = a00 - q, d1 = a11 - q, d2v = a22 - q;
    double p2 = d0 * d0 + d1 * d1 + d2v * d2v + 2.0 * p1;
    double emin, emax;
    if (!(p2 > 0.0)) { emin = q; emax = q; }
    else {
        double p = sqrt(p2 / 6.0);
        double ip = 1.0 / p;
        double b00 = d0 * ip, b11 = d1 * ip, b22 = d2v * ip;
        double b01 = a01 * ip, b02 = a02 * ip, b12 = a12 * ip;
        double detB = b00 * (b11 * b22 - b12 * b12)
                    - b01 * (b01 * b22 - b12 * b02)
                    + b02 * (b01 * b12 - b11 * b02);
        double r = 0.5 * detB;
        r = fmin(1.0, fmax(-1.0, r));
        double phi = acos(r) / 3.0;
        emax = q + 2.0 * p * cos(phi);
        emin = q + 2.0 * p * cos(phi + 2.0943951023931953);
    }
    float e0 = (float)emin, e2 = (float)emax;
    return e0 / (e2 + 1e-8f);
}

// ================= kernel 2: 8-lane cooperative exact 10-NN + density (R13) =================
__global__ void __launch_bounds__(256) k_geom2() {
    const int gt = blockIdx.x * 256 + threadIdx.x;
    const int p  = gt >> 3;
    const int l8 = gt & 7;
    const int b  = p >> 13;
    const int s  = p & (NN - 1);
    const int boff  = b * NN;
    const int cbase = b * GC;
    const unsigned gmask = 0xFFu << ((threadIdx.x & 31) & ~7);

    float4 pi = __ldg(&g_sp4[boff + s]);
    const float pix = pi.x, piy = pi.y, piz = pi.z, piw = fabsf(pi.w);
    const int orig  = g_sidx[boff + s];
    const float Tloc = g_T;

    const int cix = min(GRID - 1, max(0, (int)(pix * (float)GRID)));
    const int ciy = min(GRID - 1, max(0, (int)(piy * (float)GRID)));
    const int ciz = min(GRID - 1, max(0, (int)(piz * (float)GRID)));

    float r_est = 0.075f;
#pragma unroll
    for (int it = 0; it < 2; it++) {
        float fx = (fminf(pix + r_est, 1.0f) - fmaxf(pix - r_est, 0.0f)) / (2.0f * r_est);
        float fy = (fminf(piy + r_est, 1.0f) - fmaxf(piy - r_est, 0.0f)) / (2.0f * r_est);
        float fz = (fminf(piz + r_est, 1.0f) - fmaxf(piz - r_est, 0.0f)) / (2.0f * r_est);
        r_est = cbrtf(6.4e-4f / fmaxf(fx * fy * fz, 0.125f));
    }
    const float t_est = r_est * r_est;
    const unsigned long long GATE_EST =
        ((unsigned long long)__float_as_uint(t_est) << 32) | 0xFFFFFFFFull;
    const unsigned long long GATE_INF = 0xFFFFFFFFFFFFFFFFull;

    unsigned long long best[KNN];
    int cnt;
    float c00, c01, c02, c11, c12, c22;
    unsigned long long d10key;

    for (int R = 2;; R++) {
        bool scanned = false;

        if (R == 2) {
#pragma unroll
            for (int k = 0; k < KNN; k++) best[k] = GATE_EST;
            cnt = 0;
            int passes = 0;

            const int x0 = max(cix - 2, 0), x1 = min(cix + 2, GRID - 1);
            int rjst[4], rjen[4];
#pragma unroll
            for (int i = 0; i < 4; i++) {
                rjst[i] = 0; rjen[i] = 0;
                int q = l8 + 8 * i;
                if (q < 25) {
                    int zz = ciz + q / 5 - 2, yy = ciy + q % 5 - 2;
                    if ((unsigned)zz < GRID && (unsigned)yy < GRID) {
                        float zlo = (float)zz * HCELL, zhi = zlo + HCELL;
                        float ylo = (float)yy * HCELL, yhi = ylo + HCELL;
                        float dzl = fmaxf(0.0f, fmaxf(zlo - piz, piz - zhi));
                        float dyl = fmaxf(0.0f, fmaxf(ylo - piy, piy - yhi));
                        float rb2 = dzl * dzl + dyl * dyl;
                        if (rb2 <= t_est + PEPS) {
                            float xr = sqrtf(t_est + PEPS - rb2);
                            int xlo = (int)((pix - xr) * (float)GRID);
                            int xhi = (int)((pix + xr) * (float)GRID);
                            int xa = max(x0, xlo), xb = min(x1, xhi);
                            int crow = cbase + (zz * GRID + yy) * GRID;
                            rjst[i] = __ldg(&g_range[crow + xa].x);
                            rjen[i] = __ldg(&g_range[crow + xb].y);
                        }
                    }
                }
            }
#pragma unroll
            for (int i = 0; i < 4; i++) {
#pragma unroll 2
                for (int j = rjst[i]; j < rjen[i]; ++j) {
                    float4 pj = __ldg(&g_sp4[boff + j]);
                    float sqj = fabsf(pj.w);
                    float Tv  = (__float_as_uint(pj.w) & 0x80000000u)
                                ? Tloc : __int_as_float(0xff800000);
                    float dot = fmaf(pix, pj.x, fmaf(piy, pj.y, piz * pj.z));
                    float d2  = fmaf(-2.0f, dot, piw + sqj);
                    if (d2 <= Tv) cnt++;
                    float d2c = fmaxf(d2, 0.0f);
                    if (d2c < t_est) passes++;
                    unsigned long long key =
                        ((unsigned long long)__float_as_uint(d2c) << 32) | (unsigned)j;
                    if (key < best[KNN - 1]) {
#pragma unroll
                        for (int k = 0; k < KNN; k++) {
                            if (key < best[k]) {
                                unsigned long long tmp = best[k]; best[k] = key; key = tmp;
                            }
                        }
                    }
                }
            }

            int pall = passes;
            pall += __shfl_xor_sync(gmask, pall, 1);
            pall += __shfl_xor_sync(gmask, pall, 2);
            pall += __shfl_xor_sync(gmask, pall, 4);
            if (pall >= KNN) scanned = true;
        }

        if (!scanned) {
#pragma unroll
            for (int k = 0; k < KNN; k++) best[k] = GATE_INF;
            cnt = 0;

            const int W = 2 * R + 1;
            const int nr = W * W;
            const int x0 = max(cix - R, 0), x1 = min(cix + R, GRID - 1);
            int qy = l8, qz = 0;
            while (qy >= W) { qy -= W; qz++; }

            for (int q = l8; q < nr; q += 8) {
                int zz = ciz + qz - R, yy = ciy + qy - R;
                if ((unsigned)zz < GRID && (unsigned)yy < GRID) {
                    int crow = cbase + (zz * GRID + yy) * GRID;
                    int jst = __ldg(&g_range[crow + x0].x);
                    int jen = __ldg(&g_range[crow + x1].y);
                    for (int j = jst; j < jen; ++j) {
                        float4 pj = __ldg(&g_sp4[boff + j]);
                        float sqj = fabsf(pj.w);
                        float Tv  = (__float_as_uint(pj.w) & 0x80000000u)
                                    ? Tloc : __int_as_float(0xff800000);
                        float dot = fmaf(pix, pj.x, fmaf(piy, pj.y, piz * pj.z));
                        float d2  = fmaf(-2.0f, dot, piw + sqj);
                        if (d2 <= Tv) cnt++;
                        float d2c = fmaxf(d2, 0.0f);
                        unsigned long long key =
                            ((unsigned long long)__float_as_uint(d2c) << 32) | (unsigned)j;
                        if (key < best[KNN - 1]) {
#pragma unroll
                            for (int k = 0; k < KNN; k++) {
                                if (key < best[k]) {
                                    unsigned long long tmp = best[k]; best[k] = key; key = tmp;
                                }
                            }
                        }
                    }
                }
                qy += 8;
                while (qy >= W) { qy -= W; qz++; }
            }
        }

        c00 = c01 = c02 = c11 = c12 = c22 = 0.0f;
        d10key = GATE_INF;
#pragma unroll
        for (int round = 0; round < KNN; round++) {
            unsigned long long m = best[0];
            m = min(m, __shfl_xor_sync(gmask, m, 1));
            m = min(m, __shfl_xor_sync(gmask, m, 2));
            m = min(m, __shfl_xor_sync(gmask, m, 4));
            bool real = ((unsigned)(m & 0xFFFFFFFFull)) != 0xFFFFFFFFu;
            if (m == best[0] && real) {
                int j = (int)(unsigned)(m & 0xFFFFFFFFull);
                float4 q = __ldg(&g_sp4[boff + j]);
                float dx = q.x - pix, dy = q.y - piy, dz = q.z - piz;
                c00 = fmaf(dx, dx, c00); c01 = fmaf(dx, dy, c01); c02 = fmaf(dx, dz, c02);
                c11 = fmaf(dy, dy, c11); c12 = fmaf(dy, dz, c12); c22 = fmaf(dz, dz, c22);
#pragma unroll
                for (int k = 0; k < KNN - 1; k++) best[k] = best[k + 1];
                best[KNN - 1] = GATE_INF;
            }
            d10key = m;
        }

        float g = __int_as_float(0x7f800000);
        if (cix - R > 0)        g = fminf(g, pix - (float)(cix - R) * HCELL);
        if (cix + R < GRID - 1) g = fminf(g, (float)(cix + R + 1) * HCELL - pix);
        if (ciy - R > 0)        g = fminf(g, piy - (float)(ciy - R) * HCELL);
        if (ciy + R < GRID - 1) g = fminf(g, (float)(ciy + R + 1) * HCELL - piy);
        if (ciz - R > 0)        g = fminf(g, piz - (float)(ciz - R) * HCELL);
        if (ciz + R < GRID - 1) g = fminf(g, (float)(ciz + R + 1) * HCELL - piz);
        bool filled = ((unsigned)(d10key & 0xFFFFFFFFull)) != 0xFFFFFFFFu;
        float d10 = __uint_as_float((unsigned)(d10key >> 32));
        if (filled && d10 < g * g) break;
        if (R >= GRID) break;
    }

#pragma unroll
    for (int o = 1; o < 8; o <<= 1) {
        cnt += __shfl_xor_sync(gmask, cnt, o);
        c00 += __shfl_xor_sync(gmask, c00, o);
        c01 += __shfl_xor_sync(gmask, c01, o);
        c02 += __shfl_xor_sync(gmask, c02, o);
        c11 += __shfl_xor_sync(gmask, c11, o);
        c12 += __shfl_xor_sync(gmask, c12, o);
        c22 += __shfl_xor_sync(gmask, c22, o);
    }

    if (l8 == 0) {
        c00 = __fdiv_rn(c00, 10.0f); c01 = __fdiv_rn(c01, 10.0f); c02 = __fdiv_rn(c02, 10.0f);
        c11 = __fdiv_rn(c11, 10.0f); c12 = __fdiv_rn(c12, 10.0f); c22 = __fdiv_rn(c22, 10.0f);
        float curv = curv_from_cov(c00, c01, c02, c11, c12, c22);

        double cm   = g_cacc[b][3];
        double cden = cm > 1.0 ? cm : 1.0;
        float cx = (float)(g_cacc[b][0] / cden);
        float cy = (float)(g_cacc[b][1] / cden);
        float cz = (float)(g_cacc[b][2] / cden);
        float rx = pix - cx, ry = piy - cy, rz = piz - cz;
        float distc = __fsqrt_rn(__fadd_rn(__fadd_rn(__fmul_rn(rx, rx), __fmul_rn(ry, ry)), __fmul_rn(rz, rz)));
        float horiz = __fsqrt_rn(__fadd_rn(__fmul_rn(rx, rx), __fmul_rn(ry, ry)));
        float rad   = atan2f(ry, rx);

        bool valid = cm > 0.0;
        g_geom[orig * 6 + 0] = valid ? distc : 0.0f;
        g_geom[orig * 6 + 1] = valid ? rz    : 0.0f;
        g_geom[orig * 6 + 2] = valid ? horiz : 0.0f;
        g_geom[orig * 6 + 3] = valid ? (float)cnt : 0.0f;
        g_geom[orig * 6 + 4] = valid ? curv  : 0.0f;
        g_geom[orig * 6 + 5] = valid ? rad   : 0.0f;
    }
}

// ================= kernel 3: MLP via mma.sync tf32, 512 thr, smem weights =================
// smem floats: sX[128][76]@0 | sW1[72][136]@9728 | sW2[128][136]@19520
//              sH[128][132]@36928 | sB1@53824 | sB2@53952   (216,320 B)
#define XS   76
#define WS   136
#define HS   132
#define OX   0
#define OW1  9728
#define OW2  19520
#define OH   36928
#define OB1  53824
#define OB2  53952
#define SMEM_MMA 216320

__device__ __forceinline__ unsigned to_tf32u(float v) {
    unsigned r; asm("cvt.rna.tf32.f32 %0, %1;" : "=r"(r) : "f"(v)); return r;
}
__device__ __forceinline__ void mma8(float* c, unsigned a0, unsigned a1, unsigned a2,
                                     unsigned a3, unsigned b0, unsigned b1) {
    asm volatile(
        "mma.sync.aligned.m16n8k8.row.col.f32.tf32.tf32.f32 "
        "{%0,%1,%2,%3}, {%4,%5,%6,%7}, {%8,%9}, {%0,%1,%2,%3};"
        : "+f"(c[0]), "+f"(c[1]), "+f"(c[2]), "+f"(c[3])
        : "r"(a0), "r"(a1), "r"(a2), "r"(a3), "r"(b0), "r"(b1));
}

__global__ void __launch_bounds__(512)
k_mlp_mma(const float* __restrict__ feat,
          const float* __restrict__ W1, const float* __restrict__ b1,
          const float* __restrict__ W2, const float* __restrict__ b2,
          float* __restrict__ out) {
    extern __shared__ float sm[];
    const int tid = threadIdx.x;
    const int wid = tid >> 5;
    const int lane = tid & 31;
    const int lr = lane >> 2;          // 0..7
    const int lc = lane & 3;           // 0..3
    const int wrow  = (wid >> 1) * 16; // warp pair's 16-row stripe
    const int nh    = (wid & 1) * 8;   // n-tile offset within pair (tiles nh..nh+7)
    const int m0 = blockIdx.x * 128;

    // ---- stage inputs (tf32-rounded), 512-thread strides ----
    for (int i = tid; i < 128 * 64; i += 512) {
        int r = i >> 6, c = i & 63;
        sm[OX + r * XS + c] = __uint_as_float(to_tf32u(feat[(size_t)(m0 + r) * 64 + c]));
    }
    for (int i = tid; i < 128 * 6; i += 512) {
        int r = i / 6, c = i % 6;
        sm[OX + r * XS + 64 + c] = __uint_as_float(to_tf32u(g_geom[(size_t)(m0 + r) * 6 + c]));
    }
    if (tid < 256) {               // X pad cols 70,71 = 0
        int r = tid >> 1, c = 70 + (tid & 1);
        sm[OX + r * XS + c] = 0.0f;
    }
    for (int i = tid; i < 70 * 128; i += 512) {
        int k = i >> 7, n = i & 127;
        sm[OW1 + k * WS + n] = __uint_as_float(to_tf32u(W1[i]));
    }
    if (tid < 256) {               // W1 pad rows 70,71 = 0
        int k = 70 + (tid >> 7), n = tid & 127;
        sm[OW1 + k * WS + n] = 0.0f;
    }
    for (int i = tid; i < 128 * 128; i += 512) {
        int k = i >> 7, n = i & 127;
        sm[OW2 + k * WS + n] = __uint_as_float(to_tf32u(W2[i]));
    }
    if (tid < 128) { sm[OB1 + tid] = b1[tid]; sm[OB2 + tid] = b2[tid]; }
    __syncthreads();

    float acc[8][4];
#pragma unroll
    for (int t = 0; t < 8; t++)
#pragma unroll
        for (int c = 0; c < 4; c++) acc[t][c] = 0.0f;

    // ---- layer 1: X[128x72] @ W1t -> acc (9 k-steps, 8 n-tiles per warp) ----
    const float* xa = sm + OX + (wrow + lr) * XS;
    for (int ks = 0; ks < 9; ks++) {
        int k0 = ks * 8;
        unsigned a0 = __float_as_uint(xa[k0 + lc]);
        unsigned a1 = __float_as_uint(xa[8 * XS + k0 + lc]);
        unsigned a2 = __float_as_uint(xa[k0 + lc + 4]);
        unsigned a3 = __float_as_uint(xa[8 * XS + k0 + lc + 4]);
        const float* wb = sm + OW1 + (k0 + lc) * WS + lr;
#pragma unroll
        for (int t = 0; t < 8; t++) {
            int tt = (t << 1) | (nh >> 3);     // interleave: warp0 even tiles, warp1 odd
            unsigned b0  = __float_as_uint(wb[tt * 8]);
            unsigned b1r = __float_as_uint(wb[4 * WS + tt * 8]);
            mma8(acc[t], a0, a1, a2, a3, b0, b1r);
        }
    }

    // ---- epilogue 1: bias + relu -> H (tf32) ----
#pragma unroll
    for (int t = 0; t < 8; t++) {
        int tt = (t << 1) | (nh >> 3);
        int n0 = tt * 8 + 2 * lc;
        float bv0 = sm[OB1 + n0], bv1 = sm[OB1 + n0 + 1];
        float2 h0, h1;
        h0.x = __uint_as_float(to_tf32u(fmaxf(acc[t][0] + bv0, 0.0f)));
        h0.y = __uint_as_float(to_tf32u(fmaxf(acc[t][1] + bv1, 0.0f)));
        h1.x = __uint_as_float(to_tf32u(fmaxf(acc[t][2] + bv0, 0.0f)));
        h1.y = __uint_as_float(to_tf32u(fmaxf(acc[t][3] + bv1, 0.0f)));
        *(float2*)&sm[OH + (wrow + lr) * HS + n0]     = h0;
        *(float2*)&sm[OH + (wrow + lr + 8) * HS + n0] = h1;
    }
    __syncthreads();   // warp pairs wrote interleaved n-tiles of shared rows

#pragma unroll
    for (int t = 0; t < 8; t++)
#pragma unroll
        for (int c = 0; c < 4; c++) acc[t][c] = 0.0f;

    // ---- layer 2: H[128x128] @ W2t -> acc (16 k-steps) ----
    const float* ha = sm + OH + (wrow + lr) * HS;
    for (int ks = 0; ks < 16; ks++) {
        int k0 = ks * 8;
        unsigned a0 = __float_as_uint(ha[k0 + lc]);
        unsigned a1 = __float_as_uint(ha[8 * HS + k0 + lc]);
        unsigned a2 = __float_as_uint(ha[k0 + lc + 4]);
        unsigned a3 = __float_as_uint(ha[8 * HS + k0 + lc + 4]);
        const float* wb = sm + OW2 + (k0 + lc) * WS + lr;
#pragma unroll
        for (int t = 0; t < 8; t++) {
            int tt = (t << 1) | (nh >> 3);
            unsigned b0  = __float_as_uint(wb[tt * 8]);
            unsigned b1r = __float_as_uint(wb[4 * WS + tt * 8]);
            mma8(acc[t], a0, a1, a2, a3, b0, b1r);
        }
    }

    // ---- epilogue 2: bias + relu -> global ----
#pragma unroll
    for (int t = 0; t < 8; t++) {
        int tt = (t << 1) | (nh >> 3);
        int n0 = tt * 8 + 2 * lc;
        float bv0 = sm[OB2 + n0], bv1 = sm[OB2 + n0 + 1];
        float2 o0, o1;
        o0.x = fmaxf(acc[t][0] + bv0, 0.0f);
        o0.y = fmaxf(acc[t][1] + bv1, 0.0f);
        o1.x = fmaxf(acc[t][2] + bv0, 0.0f);
        o1.y = fmaxf(acc[t][3] + bv1, 0.0f);
        *(float2*)&out[(size_t)(m0 + wrow + lr) * 128 + n0]     = o0;
        *(float2*)&out[(size_t)(m0 + wrow + lr + 8) * 128 + n0] = o1;
    }
}

// ---------------- launch ----------------
extern "C" void kernel_launch(void* const* d_in, const int* in_sizes, int n_in,
                              void* d_out, int out_size) {
    const float* points = (const float*)d_in[0];
    const float* feat   = (const float*)d_in[1];
    const void*  mask   = d_in[2];
    const float* W1     = (const float*)d_in[3];
    const float* b1     = (const float*)d_in[4];
    const float* W2     = (const float*)d_in[5];
    const float* b2     = (const float*)d_in[6];
    float* out = (float*)d_out;

    cudaFuncSetAttribute(k_mlp_mma, cudaFuncAttributeMaxDynamicSharedMemorySize, SMEM_MMA);

    k_prep   <<<NBLKP, NTHRP>>>(points, mask);
    k_geom2  <<<(NPT * 8) / 256, 256>>>();
    k_mlp_mma<<<NPT / 128, 512, SMEM_MMA>>>(feat, W1, b1, W2, b2, out);
}